// round 7
// baseline (speedup 1.0000x reference)
#include <cuda_runtime.h>
#include <cuda_bf16.h>

// GridSampler: out[b,c,y,x] = bilinear(img[b,c], affine_grid(params[b])(y,x))
// img: (16, 8, 512, 512) fp32; params: (16, 3) fp32; out: (16, 8, 512, 512) fp32.

#define GS_B 16
#define GS_C 8
#define GS_H 512
#define GS_W 512

__global__ __launch_bounds__(256) void GridSampler_kernel(
    const float* __restrict__ img,
    const float* __restrict__ params,
    float* __restrict__ out)
{
    const int idx = blockIdx.x * blockDim.x + threadIdx.x;  // over B*H*W = 4,194,304
    const int x = idx & (GS_W - 1);
    const int y = (idx >> 9) & (GS_H - 1);
    const int b = idx >> 18;

    // Per-batch affine params (L1-cached broadcast)
    const float tx = __ldg(&params[b * 3 + 0]) * (1.0f / (float)GS_W);
    const float ty = __ldg(&params[b * 3 + 1]) * (1.0f / (float)GS_H);
    const float th = __ldg(&params[b * 3 + 2]);
    float s, c;
    sincosf(th, &s, &c);

    // Normalized grid coords, matching reference op ordering
    const float xs = (2.0f * (float)x + 1.0f) * (1.0f / (float)GS_W) - 1.0f;
    const float ys = (2.0f * (float)y + 1.0f) * (1.0f / (float)GS_H) - 1.0f;
    const float gx = c * xs - s * ys + tx;
    const float gy = s * xs + c * ys + ty;

    // Unnormalize to pixel space
    const float ix = ((gx + 1.0f) * (float)GS_W - 1.0f) * 0.5f;
    const float iy = ((gy + 1.0f) * (float)GS_H - 1.0f) * 0.5f;

    const float x0f = floorf(ix);
    const float y0f = floorf(iy);
    const int x0 = (int)x0f;
    const int y0 = (int)y0f;
    const int x1 = x0 + 1;
    const int y1 = y0 + 1;

    const float wx1 = ix - x0f;
    const float wx0 = 1.0f - wx1;
    const float wy1 = iy - y0f;
    const float wy0 = 1.0f - wy1;

    // Zero-padding: fold validity into weights (== reference's value*valid)
    const bool vx0 = (x0 >= 0) & (x0 < GS_W);
    const bool vx1 = (x1 >= 0) & (x1 < GS_W);
    const bool vy0 = (y0 >= 0) & (y0 < GS_H);
    const bool vy1 = (y1 >= 0) & (y1 < GS_H);

    const float w00 = (vx0 & vy0) ? (wy0 * wx0) : 0.0f;
    const float w01 = (vx1 & vy0) ? (wy0 * wx1) : 0.0f;
    const float w10 = (vx0 & vy1) ? (wy1 * wx0) : 0.0f;
    const float w11 = (vx1 & vy1) ? (wy1 * wx1) : 0.0f;

    const int x0c = min(max(x0, 0), GS_W - 1);
    const int x1c = min(max(x1, 0), GS_W - 1);
    const int y0c = min(max(y0, 0), GS_H - 1);
    const int y1c = min(max(y1, 0), GS_H - 1);

    // Corner offsets shared across all 8 channels
    const int o00 = y0c * GS_W + x0c;
    const int o01 = y0c * GS_W + x1c;
    const int o10 = y1c * GS_W + x0c;
    const int o11 = y1c * GS_W + x1c;

    const int plane = GS_H * GS_W;               // 262144
    const int base  = b * GS_C * plane;          // batch base
    const int oidx  = y * GS_W + x;

    #pragma unroll
    for (int ch = 0; ch < GS_C; ch++) {
        const float* __restrict__ im = img + base + ch * plane;
        const float v = w00 * __ldg(im + o00)
                      + w01 * __ldg(im + o01)
                      + w10 * __ldg(im + o10)
                      + w11 * __ldg(im + o11);
        out[base + ch * plane + oidx] = v;
    }
}

extern "C" void kernel_launch(void* const* d_in, const int* in_sizes, int n_in,
                              void* d_out, int out_size) {
    const float* img    = (const float*)d_in[0];
    const float* params = (const float*)d_in[1];
    float* out = (float*)d_out;

    const int total = GS_B * GS_H * GS_W;  // one thread per (b,y,x)
    const int threads = 256;
    const int blocks = (total + threads - 1) / threads;
    GridSampler_kernel<<<blocks, threads>>>(img, params, out);
}

// round 8
// speedup vs baseline: 1.8310x; 1.8310x over previous
#include <cuda_runtime.h>
#include <cuda_bf16.h>

// GridSampler: out[b,c,y,x] = bilinear(img[b,c], affine_grid(params[b])(y,x))
// img: (16, 8, 512, 512) fp32; params: (16, 3) fp32; out: (16, 8, 512, 512) fp32.
//
// R7: 2D warp tiling. Each warp owns an 8x4 pixel patch (lanes = 8 wide x 4 tall),
// each block owns a 32x8 tile (8 warps in a 4x2 arrangement). This shrinks the
// per-warp gather footprint from ~32 rows x 1-2 cols (rotation-dependent) to
// ~13x13 px worst case, cutting L1/L2 sector amplification ~2.5-3x.

#define GS_B 16
#define GS_C 8
#define GS_H 512
#define GS_W 512

__global__ __launch_bounds__(256) void GridSampler_kernel(
    const float* __restrict__ img,
    const float* __restrict__ params,
    float* __restrict__ out)
{
    // ---- 2D warp-tiled index mapping ----
    const int lane = threadIdx.x & 31;
    const int warp = threadIdx.x >> 5;          // 0..7
    const int lx = lane & 7;                    // 0..7  (x within warp patch)
    const int ly = lane >> 3;                   // 0..3  (y within warp patch)
    const int wx = (warp & 3) << 3;             // warp patch origin x in block tile (0,8,16,24)
    const int wy = (warp >> 2) << 2;            // warp patch origin y in block tile (0,4)

    const int x = (blockIdx.x << 5) + wx + lx;  // block tile: 32 wide
    const int y = (blockIdx.y << 3) + wy + ly;  // block tile: 8 tall
    const int b = blockIdx.z;

    // Per-batch affine params (L1-cached broadcast)
    const float tx = __ldg(&params[b * 3 + 0]) * (1.0f / (float)GS_W);
    const float ty = __ldg(&params[b * 3 + 1]) * (1.0f / (float)GS_H);
    const float th = __ldg(&params[b * 3 + 2]);
    float s, c;
    sincosf(th, &s, &c);

    // Normalized grid coords, matching reference op ordering
    const float xs = (2.0f * (float)x + 1.0f) * (1.0f / (float)GS_W) - 1.0f;
    const float ys = (2.0f * (float)y + 1.0f) * (1.0f / (float)GS_H) - 1.0f;
    const float gx = c * xs - s * ys + tx;
    const float gy = s * xs + c * ys + ty;

    // Unnormalize to pixel space
    const float ix = ((gx + 1.0f) * (float)GS_W - 1.0f) * 0.5f;
    const float iy = ((gy + 1.0f) * (float)GS_H - 1.0f) * 0.5f;

    const float x0f = floorf(ix);
    const float y0f = floorf(iy);
    const int x0 = (int)x0f;
    const int y0 = (int)y0f;
    const int x1 = x0 + 1;
    const int y1 = y0 + 1;

    const float wx1 = ix - x0f;
    const float wx0 = 1.0f - wx1;
    const float wy1 = iy - y0f;
    const float wy0 = 1.0f - wy1;

    // Zero-padding: fold validity into weights (== reference's value*valid)
    const bool vx0 = (x0 >= 0) & (x0 < GS_W);
    const bool vx1 = (x1 >= 0) & (x1 < GS_W);
    const bool vy0 = (y0 >= 0) & (y0 < GS_H);
    const bool vy1 = (y1 >= 0) & (y1 < GS_H);

    const float w00 = (vx0 & vy0) ? (wy0 * wx0) : 0.0f;
    const float w01 = (vx1 & vy0) ? (wy0 * wx1) : 0.0f;
    const float w10 = (vx0 & vy1) ? (wy1 * wx0) : 0.0f;
    const float w11 = (vx1 & vy1) ? (wy1 * wx1) : 0.0f;

    const int x0c = min(max(x0, 0), GS_W - 1);
    const int x1c = min(max(x1, 0), GS_W - 1);
    const int y0c = min(max(y0, 0), GS_H - 1);
    const int y1c = min(max(y1, 0), GS_H - 1);

    // Corner offsets shared across all 8 channels
    const int o00 = y0c * GS_W + x0c;
    const int o01 = y0c * GS_W + x1c;
    const int o10 = y1c * GS_W + x0c;
    const int o11 = y1c * GS_W + x1c;

    const int plane = GS_H * GS_W;               // 262144
    const int base  = b * GS_C * plane;          // batch base
    const int oidx  = y * GS_W + x;

    #pragma unroll
    for (int ch = 0; ch < GS_C; ch++) {
        const float* __restrict__ im = img + base + ch * plane;
        const float v = w00 * __ldg(im + o00)
                      + w01 * __ldg(im + o01)
                      + w10 * __ldg(im + o10)
                      + w11 * __ldg(im + o11);
        out[base + ch * plane + oidx] = v;
    }
}

extern "C" void kernel_launch(void* const* d_in, const int* in_sizes, int n_in,
                              void* d_out, int out_size) {
    const float* img    = (const float*)d_in[0];
    const float* params = (const float*)d_in[1];
    float* out = (float*)d_out;

    dim3 block(256);
    dim3 grid(GS_W / 32, GS_H / 8, GS_B);   // 16 x 64 x 16 = 16384 blocks
    GridSampler_kernel<<<grid, block>>>(img, params, out);
}

// round 10
// speedup vs baseline: 1.9381x; 1.0585x over previous
#include <cuda_runtime.h>
#include <cuda_bf16.h>

// GridSampler: out[b,c,y,x] = bilinear(img[b,c], affine_grid(params[b])(y,x))
// img: (16, 8, 512, 512) fp32; params: (16, 3) fp32; out: (16, 8, 512, 512) fp32.
//
// R9 (= R8 resubmit after infra failure): SMEM tile staging. Each 512-thread
// block handles a 32x16 output tile. The affine input footprint bounding box
// (<= 39x39 px) of all 8 channels is staged into SMEM with coalesced loads;
// bilinear gathers then run on SMEM instead of the sector-amplified L1 path.

#define GS_B 16
#define GS_C 8
#define GS_H 512
#define GS_W 512

#define TILE_X 32
#define TILE_Y 16
#define STW 39          // staged tile width (stride)
#define STH 39          // staged tile height
#define SPLANE (STH * STW)   // 1521 floats per channel

__global__ __launch_bounds__(512, 4) void GridSampler_kernel(
    const float* __restrict__ img,
    const float* __restrict__ params,
    float* __restrict__ out)
{
    __shared__ float tile[GS_C * SPLANE];   // 8 * 1521 * 4 = 48672 B (< 48KB static limit)

    const int tid  = threadIdx.x;
    const int lane = tid & 31;
    const int warp = tid >> 5;               // 0..15
    // warp owns an 8x4 pixel patch; warps arranged 4x4 over the 32x16 tile
    const int lx = lane & 7;
    const int ly = lane >> 3;
    const int wx = (warp & 3) << 3;
    const int wy = (warp >> 2) << 2;

    const int X0 = blockIdx.x * TILE_X;
    const int Y0 = blockIdx.y * TILE_Y;
    const int b  = blockIdx.z;
    const int x  = X0 + wx + lx;
    const int y  = Y0 + wy + ly;

    // Per-batch affine params
    const float tx = __ldg(&params[b * 3 + 0]) * (1.0f / (float)GS_W);
    const float ty = __ldg(&params[b * 3 + 1]) * (1.0f / (float)GS_H);
    const float th = __ldg(&params[b * 3 + 2]);
    float s, c;
    sincosf(th, &s, &c);

    // Pixel-space sample coordinate for integer output pixel (px,py).
    auto sample_coord = [&](int px, int py, float& oix, float& oiy) {
        const float xs = (2.0f * (float)px + 1.0f) * (1.0f / (float)GS_W) - 1.0f;
        const float ys = (2.0f * (float)py + 1.0f) * (1.0f / (float)GS_H) - 1.0f;
        const float gx = c * xs - s * ys + tx;
        const float gy = s * xs + c * ys + ty;
        oix = ((gx + 1.0f) * (float)GS_W - 1.0f) * 0.5f;
        oiy = ((gy + 1.0f) * (float)GS_H - 1.0f) * 0.5f;
    };

    // Bounding box of the tile's input footprint: affine => extrema at corners.
    float cix0, ciy0, cix1, ciy1, cix2, ciy2, cix3, ciy3;
    sample_coord(X0,             Y0,              cix0, ciy0);
    sample_coord(X0 + TILE_X-1,  Y0,              cix1, ciy1);
    sample_coord(X0,             Y0 + TILE_Y-1,   cix2, ciy2);
    sample_coord(X0 + TILE_X-1,  Y0 + TILE_Y-1,   cix3, ciy3);
    const float ixmin = fminf(fminf(cix0, cix1), fminf(cix2, cix3));
    const float ixmax = fmaxf(fmaxf(cix0, cix1), fmaxf(cix2, cix3));
    const float iymin = fminf(fminf(ciy0, ciy1), fminf(ciy2, ciy3));
    const float iymax = fmaxf(fmaxf(ciy0, ciy1), fmaxf(ciy2, ciy3));

    // -1 / +2 margins cover floor() + bilinear x1 + fp rounding of corner eval.
    const int bx0 = (int)floorf(ixmin) - 1;
    const int by0 = (int)floorf(iymin) - 1;
    const int bx1 = (int)floorf(ixmax) + 2;
    const int by1 = (int)floorf(iymax) + 2;
    const int w = min(bx1 - bx0 + 1, STW);   // <= 39 by construction (31|c|+15|s|+4)
    const int h = min(by1 - by0 + 1, STH);

    const int plane = GS_H * GS_W;           // 262144
    const int base  = b * GS_C * plane;
    const float* __restrict__ imb = img + base;

    // ---- Stage: coalesced loads of the footprint box, all 8 channels ----
    // warps -> rows, lanes -> cols. Border-clamped; any sample that would
    // read outside the image gets weight 0 below, so clamped values are inert.
    for (int r = warp; r < h; r += 16) {
        const int yy = min(max(by0 + r, 0), GS_H - 1);
        const float* __restrict__ srow = imb + yy * GS_W;
        float* __restrict__ drow = tile + r * STW;
        for (int i = lane; i < w; i += 32) {
            const int xx = min(max(bx0 + i, 0), GS_W - 1);
            const float* __restrict__ sp = srow + xx;
            #pragma unroll
            for (int ch = 0; ch < GS_C; ch++)
                drow[ch * SPLANE + i] = __ldg(sp + ch * plane);
        }
    }
    __syncthreads();

    // ---- Sample ----
    float ix, iy;
    sample_coord(x, y, ix, iy);

    const float x0f = floorf(ix);
    const float y0f = floorf(iy);
    const int x0 = (int)x0f;
    const int y0 = (int)y0f;
    const int x1 = x0 + 1;
    const int y1 = y0 + 1;

    const float wx1 = ix - x0f;
    const float wx0 = 1.0f - wx1;
    const float wy1 = iy - y0f;
    const float wy0 = 1.0f - wy1;

    // Zero-padding folded into weights (== reference's value*valid)
    const bool vx0 = (x0 >= 0) & (x0 < GS_W);
    const bool vx1 = (x1 >= 0) & (x1 < GS_W);
    const bool vy0 = (y0 >= 0) & (y0 < GS_H);
    const bool vy1 = (y1 >= 0) & (y1 < GS_H);

    const float w00 = (vx0 & vy0) ? (wy0 * wx0) : 0.0f;
    const float w01 = (vx1 & vy0) ? (wy0 * wx1) : 0.0f;
    const float w10 = (vx0 & vy1) ? (wy1 * wx0) : 0.0f;
    const float w11 = (vx1 & vy1) ? (wy1 * wx1) : 0.0f;

    const int x0c = min(max(x0, 0), GS_W - 1);
    const int x1c = min(max(x1, 0), GS_W - 1);
    const int y0c = min(max(y0, 0), GS_H - 1);
    const int y1c = min(max(y1, 0), GS_H - 1);

    // SMEM window indices. Valid samples are in-window by construction
    // (per-pixel coord is a convex combination of the corner coords);
    // weight-0 samples are clamped into the staged (finite) region so the
    // 0-weight multiply stays exactly 0.
    const int i0 = min(max(x0c - bx0, 0), w - 1);
    const int i1 = min(max(x1c - bx0, 0), w - 1);
    const int j0 = min(max(y0c - by0, 0), h - 1);
    const int j1 = min(max(y1c - by0, 0), h - 1);

    const int o00 = j0 * STW + i0;
    const int o01 = j0 * STW + i1;
    const int o10 = j1 * STW + i0;
    const int o11 = j1 * STW + i1;

    const int oidx = base + y * GS_W + x;

    #pragma unroll
    for (int ch = 0; ch < GS_C; ch++) {
        const float* __restrict__ t = tile + ch * SPLANE;
        const float v = w00 * t[o00] + w01 * t[o01]
                      + w10 * t[o10] + w11 * t[o11];
        out[oidx + ch * plane] = v;
    }
}

extern "C" void kernel_launch(void* const* d_in, const int* in_sizes, int n_in,
                              void* d_out, int out_size) {
    const float* img    = (const float*)d_in[0];
    const float* params = (const float*)d_in[1];
    float* out = (float*)d_out;

    dim3 block(512);
    dim3 grid(GS_W / TILE_X, GS_H / TILE_Y, GS_B);  // 16 x 32 x 16 = 8192 blocks
    GridSampler_kernel<<<grid, block>>>(img, params, out);
}

// round 12
// speedup vs baseline: 2.2104x; 1.1405x over previous
#include <cuda_runtime.h>
#include <cuda_bf16.h>
#include <cstdint>

// GridSampler: out[b,c,y,x] = bilinear(img[b,c], affine_grid(params[b])(y,x))
// img: (16, 8, 512, 512) fp32; params: (16, 3) fp32; out: (16, 8, 512, 512) fp32.
//
// R11: cp.async (LDGSTS) staging. Each 512-thread block handles a 32x16 output
// tile. The affine footprint is covered by a fixed 44x40 window, clamped fully
// inside the image and 16B-aligned, so staging is a dense block copy done with
// cp.async.cg 16B ops (1 instr / 16B, L1-bypass, no register round-trip) —
// ~110 warp-ops/block vs ~760 LDG+STS+clamp in the R9 software-staging path.

#define GS_B 16
#define GS_C 8
#define GS_H 512
#define GS_W 512

#define TILE_X 32
#define TILE_Y 16

#define BOXW 44                    // 11 x 16B per row, covers span<=43 after align
#define BOXH 40                    // covers row span<=40
#define CPLANE (BOXW * BOXH)       // 1760 floats per channel
#define SMEM_BYTES (GS_C * CPLANE * 4)       // 56320 B (dynamic smem)
#define CHUNKS_PER_ROW (BOXW / 4)            // 11
#define CHUNKS_PER_CH (CHUNKS_PER_ROW * BOXH)  // 440
#define CHUNKS_TOTAL (CHUNKS_PER_CH * GS_C)    // 3520

__device__ __forceinline__ uint32_t smem_u32(const void* p) {
    uint32_t a;
    asm("{ .reg .u64 t; cvta.to.shared.u64 t, %1; cvt.u32.u64 %0, t; }"
        : "=r"(a) : "l"(p));
    return a;
}

__global__ __launch_bounds__(512, 4) void GridSampler_kernel(
    const float* __restrict__ img,
    const float* __restrict__ params,
    float* __restrict__ out)
{
    extern __shared__ float tile[];          // [8][40][44] floats

    const int tid  = threadIdx.x;
    const int lane = tid & 31;
    const int warp = tid >> 5;               // 0..15
    const int lx = lane & 7;
    const int ly = lane >> 3;
    const int wx = (warp & 3) << 3;
    const int wy = (warp >> 2) << 2;

    const int X0 = blockIdx.x * TILE_X;
    const int Y0 = blockIdx.y * TILE_Y;
    const int b  = blockIdx.z;
    const int x  = X0 + wx + lx;
    const int y  = Y0 + wy + ly;

    // Per-batch affine params
    const float tx = __ldg(&params[b * 3 + 0]) * (1.0f / (float)GS_W);
    const float ty = __ldg(&params[b * 3 + 1]) * (1.0f / (float)GS_H);
    const float th = __ldg(&params[b * 3 + 2]);
    float s, c;
    sincosf(th, &s, &c);

    auto sample_coord = [&](int px, int py, float& oix, float& oiy) {
        const float xs = (2.0f * (float)px + 1.0f) * (1.0f / (float)GS_W) - 1.0f;
        const float ys = (2.0f * (float)py + 1.0f) * (1.0f / (float)GS_H) - 1.0f;
        const float gx = c * xs - s * ys + tx;
        const float gy = s * xs + c * ys + ty;
        oix = ((gx + 1.0f) * (float)GS_W - 1.0f) * 0.5f;
        oiy = ((gy + 1.0f) * (float)GS_H - 1.0f) * 0.5f;
    };

    // Footprint bbox: affine => extrema at tile corners.
    float cix0, ciy0, cix1, ciy1, cix2, ciy2, cix3, ciy3;
    sample_coord(X0,            Y0,             cix0, ciy0);
    sample_coord(X0 + TILE_X-1, Y0,             cix1, ciy1);
    sample_coord(X0,            Y0 + TILE_Y-1,  cix2, ciy2);
    sample_coord(X0 + TILE_X-1, Y0 + TILE_Y-1,  cix3, ciy3);
    const float ixmin = fminf(fminf(cix0, cix1), fminf(cix2, cix3));
    const float iymin = fminf(fminf(ciy0, ciy1), fminf(ciy2, ciy3));
    const int bx0 = (int)floorf(ixmin) - 1;   // needed cols in [bx0, bx0+39]
    const int by0 = (int)floorf(iymin) - 1;   // needed rows in [by0, by0+39]

    // Fixed-size staged window, 16B-aligned and fully inside the image.
    // Coverage proof: valid corner cols lie in [max(bx0,0), min(bx0+39,511)];
    // clamping preserves coverage at both extremes (see analysis).
    const int cbx = min(max(bx0 & ~3, 0), GS_W - BOXW);   // [0, 468], mult of 4
    const int cby = min(max(by0, 0), GS_H - BOXH);        // [0, 472]

    const int plane = GS_H * GS_W;
    const int base  = b * GS_C * plane;
    const float* __restrict__ src0 = img + base + cby * GS_W + cbx;
    const uint32_t smem0 = smem_u32(tile);

    // ---- Stage: dense aligned block copy via cp.async.cg (16B), L1-bypass ----
    #pragma unroll
    for (int k = 0; k < 7; k++) {
        const int idx = tid + k * 512;
        if (idx < CHUNKS_TOTAL) {
            const int ch  = idx / CHUNKS_PER_CH;
            const int rem = idx - ch * CHUNKS_PER_CH;
            const int r   = rem / CHUNKS_PER_ROW;
            const int cc  = rem - r * CHUNKS_PER_ROW;
            const float* g = src0 + ch * plane + r * GS_W + (cc << 2);
            const uint32_t sa = smem0 + (uint32_t)(ch * CPLANE + r * BOXW + (cc << 2)) * 4u;
            asm volatile("cp.async.cg.shared.global [%0], [%1], 16;"
                         :: "r"(sa), "l"(g) : "memory");
        }
    }
    asm volatile("cp.async.commit_group;" ::: "memory");

    // ---- per-pixel weights/indices while LDGSTS is in flight ----
    float ix, iy;
    sample_coord(x, y, ix, iy);

    const float x0f = floorf(ix);
    const float y0f = floorf(iy);
    const int x0 = (int)x0f;
    const int y0 = (int)y0f;
    const int x1 = x0 + 1;
    const int y1 = y0 + 1;

    const float wx1 = ix - x0f;
    const float wx0 = 1.0f - wx1;
    const float wy1 = iy - y0f;
    const float wy0 = 1.0f - wy1;

    // Zero-padding folded into weights (== reference's value*valid)
    const bool vx0 = (x0 >= 0) & (x0 < GS_W);
    const bool vx1 = (x1 >= 0) & (x1 < GS_W);
    const bool vy0 = (y0 >= 0) & (y0 < GS_H);
    const bool vy1 = (y1 >= 0) & (y1 < GS_H);

    const float w00 = (vx0 & vy0) ? (wy0 * wx0) : 0.0f;
    const float w01 = (vx1 & vy0) ? (wy0 * wx1) : 0.0f;
    const float w10 = (vx0 & vy1) ? (wy1 * wx0) : 0.0f;
    const float w11 = (vx1 & vy1) ? (wy1 * wx1) : 0.0f;

    // Window indices. Valid corners land in-window by construction; weight-0
    // corners are clamped into the staged (finite) region so 0*value stays 0.
    const int i0 = min(max(x0 - cbx, 0), BOXW - 1);
    const int i1 = min(max(x1 - cbx, 0), BOXW - 1);
    const int j0 = min(max(y0 - cby, 0), BOXH - 1);
    const int j1 = min(max(y1 - cby, 0), BOXH - 1);

    const int o00 = j0 * BOXW + i0;
    const int o01 = j0 * BOXW + i1;
    const int o10 = j1 * BOXW + i0;
    const int o11 = j1 * BOXW + i1;

    // ---- wait for staging, then sample ----
    asm volatile("cp.async.wait_group 0;" ::: "memory");
    __syncthreads();

    const int oidx = base + y * GS_W + x;

    #pragma unroll
    for (int ch = 0; ch < GS_C; ch++) {
        const float* __restrict__ t = tile + ch * CPLANE;
        const float v = w00 * t[o00] + w01 * t[o01]
                      + w10 * t[o10] + w11 * t[o11];
        out[oidx + ch * plane] = v;
    }
}

extern "C" void kernel_launch(void* const* d_in, const int* in_sizes, int n_in,
                              void* d_out, int out_size) {
    const float* img    = (const float*)d_in[0];
    const float* params = (const float*)d_in[1];
    float* out = (float*)d_out;

    static bool attr_set = false;
    // Setting a func attribute is idempotent and host-side; safe under capture.
    cudaFuncSetAttribute(GridSampler_kernel,
                         cudaFuncAttributeMaxDynamicSharedMemorySize, SMEM_BYTES);
    (void)attr_set;

    dim3 block(512);
    dim3 grid(GS_W / TILE_X, GS_H / TILE_Y, GS_B);  // 16 x 32 x 16 = 8192 blocks
    GridSampler_kernel<<<grid, block, SMEM_BYTES>>>(img, params, out);
}

// round 13
// speedup vs baseline: 2.3044x; 1.0425x over previous
#include <cuda_runtime.h>
#include <cuda_bf16.h>
#include <cstdint>

// GridSampler: out[b,c,y,x] = bilinear(img[b,c], affine_grid(params[b])(y,x))
// img: (16, 8, 512, 512) fp32; params: (16, 3) fp32; out: (16, 8, 512, 512) fp32.
//
// R12: 32x32 tile / 1024-thread block. Footprint box 52x48 (amplification
// 2.44x vs 3.44x), cp.async.cg staging with ONE tid/13 divide per thread
// (threads 0..623 own a fixed (row,chunk) slot, 8 channel-stepped cp.asyncs),
// analytic bbox from the affine Jacobian, dynamic row count h<=48.

#define GS_B 16
#define GS_C 8
#define GS_H 512
#define GS_W 512

#define TILE 32                      // 32x32 output tile
#define BOXW 52                      // 13 x 16B chunks; covers col span<=48 (+<=3 align)
#define BOXH 48                      // covers row span<=48
#define CHUNKW 13
#define CPLANE (BOXW * BOXH)         // 2496 floats per channel
#define SMEM_BYTES (GS_C * CPLANE * 4)   // 79872 B
#define ROW_THREADS (CHUNKW * BOXH)  // 624 staging threads

__device__ __forceinline__ uint32_t smem_u32(const void* p) {
    uint32_t a;
    asm("{ .reg .u64 t; cvta.to.shared.u64 t, %1; cvt.u32.u64 %0, t; }"
        : "=r"(a) : "l"(p));
    return a;
}

__global__ __launch_bounds__(1024, 2) void GridSampler_kernel(
    const float* __restrict__ img,
    const float* __restrict__ params,
    float* __restrict__ out)
{
    extern __shared__ float tile[];          // [8][48][52] floats

    const int tid  = threadIdx.x;
    const int lane = tid & 31;
    const int warp = tid >> 5;               // 0..31
    // 8x4 lane patch, warps arranged 4x8 over the 32x32 tile (LDS-conflict friendly)
    const int lx = lane & 7;
    const int ly = lane >> 3;
    const int wx = (warp & 3) << 3;
    const int wy = (warp >> 2) << 2;

    const int X0 = blockIdx.x * TILE;
    const int Y0 = blockIdx.y * TILE;
    const int b  = blockIdx.z;
    const int x  = X0 + wx + lx;
    const int y  = Y0 + wy + ly;

    // Per-batch affine params
    const float tx = __ldg(&params[b * 3 + 0]) * (1.0f / (float)GS_W);
    const float ty = __ldg(&params[b * 3 + 1]) * (1.0f / (float)GS_H);
    const float th = __ldg(&params[b * 3 + 2]);
    float s, c;
    sincosf(th, &s, &c);

    auto sample_coord = [&](int px, int py, float& oix, float& oiy) {
        const float xs = (2.0f * (float)px + 1.0f) * (1.0f / (float)GS_W) - 1.0f;
        const float ys = (2.0f * (float)py + 1.0f) * (1.0f / (float)GS_H) - 1.0f;
        const float gx = c * xs - s * ys + tx;
        const float gy = s * xs + c * ys + ty;
        oix = ((gx + 1.0f) * (float)GS_W - 1.0f) * 0.5f;
        oiy = ((gy + 1.0f) * (float)GS_H - 1.0f) * 0.5f;
    };

    // Analytic footprint bbox: +1 output px in x moves (c,s) input px,
    // +1 in y moves (-s,c). Edge length 31 px. Margins -1/+2 absorb fp delta.
    float ix00, iy00;
    sample_coord(X0, Y0, ix00, iy00);
    const float ec = 31.0f * c;
    const float es = 31.0f * s;
    const float ixmin = ix00 + fminf(ec, 0.0f) + fminf(-es, 0.0f);
    const float iymin = iy00 + fminf(es, 0.0f) + fminf(ec, 0.0f);
    const float iymax = iy00 + fmaxf(es, 0.0f) + fmaxf(ec, 0.0f);

    const int bx0 = (int)floorf(ixmin) - 1;
    const int by0 = (int)floorf(iymin) - 1;
    const int by1 = (int)floorf(iymax) + 2;
    const int h   = min(by1 - by0 + 1, BOXH);        // <= 48 by construction

    // Staged window: cols fixed 52 (16B-aligned), rows dynamic h.
    const int cbx = min(max(bx0 & ~3, 0), GS_W - BOXW);
    const int cby = min(max(by0, 0), GS_H - h);

    const int plane = GS_H * GS_W;
    const int base  = b * GS_C * plane;

    // ---- Stage: threads 0..623 own one (row,chunk); 8 channel-stepped cp.asyncs ----
    if (tid < ROW_THREADS) {
        const int r  = tid / CHUNKW;                  // single divide, reused 8x
        const int cc = tid - r * CHUNKW;
        if (r < h) {
            const float* g = img + base + (cby + r) * GS_W + cbx + (cc << 2);
            uint32_t sa = smem_u32(tile) + (uint32_t)(r * BOXW + (cc << 2)) * 4u;
            #pragma unroll
            for (int ch = 0; ch < GS_C; ch++) {
                asm volatile("cp.async.cg.shared.global [%0], [%1], 16;"
                             :: "r"(sa), "l"(g) : "memory");
                g  += plane;
                sa += CPLANE * 4u;
            }
        }
    }
    asm volatile("cp.async.commit_group;" ::: "memory");

    // ---- per-pixel weights/indices while LDGSTS is in flight ----
    float ix, iy;
    sample_coord(x, y, ix, iy);

    const float x0f = floorf(ix);
    const float y0f = floorf(iy);
    const int x0 = (int)x0f;
    const int y0 = (int)y0f;
    const int x1 = x0 + 1;
    const int y1 = y0 + 1;

    const float wx1 = ix - x0f;
    const float wx0 = 1.0f - wx1;
    const float wy1 = iy - y0f;
    const float wy0 = 1.0f - wy1;

    // Zero-padding folded into weights (== reference's value*valid)
    const bool vx0 = (x0 >= 0) & (x0 < GS_W);
    const bool vx1 = (x1 >= 0) & (x1 < GS_W);
    const bool vy0 = (y0 >= 0) & (y0 < GS_H);
    const bool vy1 = (y1 >= 0) & (y1 < GS_H);

    const float w00 = (vx0 & vy0) ? (wy0 * wx0) : 0.0f;
    const float w01 = (vx1 & vy0) ? (wy0 * wx1) : 0.0f;
    const float w10 = (vx0 & vy1) ? (wy1 * wx0) : 0.0f;
    const float w11 = (vx1 & vy1) ? (wy1 * wx1) : 0.0f;

    // Window indices. Valid corners land in-window by construction; weight-0
    // corners clamp into the freshly staged region (rows < h) so 0*v stays 0.
    const int i0 = min(max(x0 - cbx, 0), BOXW - 1);
    const int i1 = min(max(x1 - cbx, 0), BOXW - 1);
    const int j0 = min(max(y0 - cby, 0), h - 1);
    const int j1 = min(max(y1 - cby, 0), h - 1);

    const int o00 = j0 * BOXW + i0;
    const int o01 = j0 * BOXW + i1;
    const int o10 = j1 * BOXW + i0;
    const int o11 = j1 * BOXW + i1;

    // ---- wait for staging, then sample ----
    asm volatile("cp.async.wait_group 0;" ::: "memory");
    __syncthreads();

    const int oidx = base + y * GS_W + x;

    #pragma unroll
    for (int ch = 0; ch < GS_C; ch++) {
        const float* __restrict__ t = tile + ch * CPLANE;
        const float v = w00 * t[o00] + w01 * t[o01]
                      + w10 * t[o10] + w11 * t[o11];
        out[oidx + ch * plane] = v;
    }
}

extern "C" void kernel_launch(void* const* d_in, const int* in_sizes, int n_in,
                              void* d_out, int out_size) {
    const float* img    = (const float*)d_in[0];
    const float* params = (const float*)d_in[1];
    float* out = (float*)d_out;

    cudaFuncSetAttribute(GridSampler_kernel,
                         cudaFuncAttributeMaxDynamicSharedMemorySize, SMEM_BYTES);

    dim3 block(1024);
    dim3 grid(GS_W / TILE, GS_H / TILE, GS_B);  // 16 x 16 x 16 = 4096 blocks
    GridSampler_kernel<<<grid, block, SMEM_BYTES>>>(img, params, out);
}

// round 16
// speedup vs baseline: 2.5381x; 1.1014x over previous
#include <cuda_runtime.h>
#include <cuda_bf16.h>
#include <cstdint>

// GridSampler: out[b,c,y,x] = bilinear(img[b,c], affine_grid(params[b])(y,x))
// img: (16, 8, 512, 512) fp32; params: (16, 3) fp32; out: (16, 8, 512, 512) fp32.
//
// R14 (= R13 resubmit after infra failure): channel-pipelined staging.
// 32x32 tile / 52x48 window / cp.async.cg staging as R12, but the 8 channels
// are staged as 4 cp.async groups of 2 channels and consumed with
// wait_group 3/2/1/0 + barrier between groups: exposed staging latency is
// ~ the first group only; the remaining 3/4 overlaps sampling + stores.

#define GS_B 16
#define GS_C 8
#define GS_H 512
#define GS_W 512

#define TILE 32                      // 32x32 output tile
#define BOXW 52                      // 13 x 16B chunks; covers col span<=48 (+<=3 align)
#define BOXH 48                      // covers row span<=48
#define CHUNKW 13
#define CPLANE (BOXW * BOXH)         // 2496 floats per channel
#define SMEM_BYTES (GS_C * CPLANE * 4)   // 79872 B
#define ROW_THREADS (CHUNKW * BOXH)  // 624 staging threads

__device__ __forceinline__ uint32_t smem_u32(const void* p) {
    uint32_t a;
    asm("{ .reg .u64 t; cvta.to.shared.u64 t, %1; cvt.u32.u64 %0, t; }"
        : "=r"(a) : "l"(p));
    return a;
}

__global__ __launch_bounds__(1024, 2) void GridSampler_kernel(
    const float* __restrict__ img,
    const float* __restrict__ params,
    float* __restrict__ out)
{
    extern __shared__ float tile[];          // [8][48][52] floats

    const int tid  = threadIdx.x;
    const int lane = tid & 31;
    const int warp = tid >> 5;               // 0..31
    const int lx = lane & 7;
    const int ly = lane >> 3;
    const int wx = (warp & 3) << 3;
    const int wy = (warp >> 2) << 2;

    const int X0 = blockIdx.x * TILE;
    const int Y0 = blockIdx.y * TILE;
    const int b  = blockIdx.z;
    const int x  = X0 + wx + lx;
    const int y  = Y0 + wy + ly;

    // Per-batch affine params
    const float tx = __ldg(&params[b * 3 + 0]) * (1.0f / (float)GS_W);
    const float ty = __ldg(&params[b * 3 + 1]) * (1.0f / (float)GS_H);
    const float th = __ldg(&params[b * 3 + 2]);
    float s, c;
    sincosf(th, &s, &c);

    auto sample_coord = [&](int px, int py, float& oix, float& oiy) {
        const float xs = (2.0f * (float)px + 1.0f) * (1.0f / (float)GS_W) - 1.0f;
        const float ys = (2.0f * (float)py + 1.0f) * (1.0f / (float)GS_H) - 1.0f;
        const float gx = c * xs - s * ys + tx;
        const float gy = s * xs + c * ys + ty;
        oix = ((gx + 1.0f) * (float)GS_W - 1.0f) * 0.5f;
        oiy = ((gy + 1.0f) * (float)GS_H - 1.0f) * 0.5f;
    };

    // Analytic footprint bbox via affine Jacobian; margins -1/+2 absorb fp delta.
    float ix00, iy00;
    sample_coord(X0, Y0, ix00, iy00);
    const float ec = 31.0f * c;
    const float es = 31.0f * s;
    const float ixmin = ix00 + fminf(ec, 0.0f) + fminf(-es, 0.0f);
    const float iymin = iy00 + fminf(es, 0.0f) + fminf(ec, 0.0f);
    const float iymax = iy00 + fmaxf(es, 0.0f) + fmaxf(ec, 0.0f);

    const int bx0 = (int)floorf(ixmin) - 1;
    const int by0 = (int)floorf(iymin) - 1;
    const int by1 = (int)floorf(iymax) + 2;
    const int h   = min(by1 - by0 + 1, BOXH);        // <= 48 by construction

    const int cbx = min(max(bx0 & ~3, 0), GS_W - BOXW);
    const int cby = min(max(by0, 0), GS_H - h);

    const int plane = GS_H * GS_W;
    const int base  = b * GS_C * plane;

    // ---- Stage: 4 cp.async groups of 2 channels each ----
    const bool do_stage0 = (tid < ROW_THREADS);
    int r = 0, cc = 0;
    if (do_stage0) { r = tid / CHUNKW; cc = tid - r * CHUNKW; }
    const bool do_stage = do_stage0 && (r < h);
    const float* g0 = img + base + (cby + r) * GS_W + cbx + (cc << 2);
    uint32_t sa0 = smem_u32(tile) + (uint32_t)(r * BOXW + (cc << 2)) * 4u;

    #pragma unroll
    for (int grp = 0; grp < 4; grp++) {
        if (do_stage) {
            const float* g = g0 + (2 * grp) * plane;
            uint32_t sa = sa0 + (uint32_t)(2 * grp) * (CPLANE * 4u);
            asm volatile("cp.async.cg.shared.global [%0], [%1], 16;"
                         :: "r"(sa), "l"(g) : "memory");
            asm volatile("cp.async.cg.shared.global [%0], [%1], 16;"
                         :: "r"(sa + CPLANE * 4u), "l"(g + plane) : "memory");
        }
        asm volatile("cp.async.commit_group;" ::: "memory");  // uniform across block
    }

    // ---- per-pixel weights/indices while group 0 is in flight ----
    float ix, iy;
    sample_coord(x, y, ix, iy);

    const float x0f = floorf(ix);
    const float y0f = floorf(iy);
    const int x0 = (int)x0f;
    const int y0 = (int)y0f;
    const int x1 = x0 + 1;
    const int y1 = y0 + 1;

    const float wx1 = ix - x0f;
    const float wx0 = 1.0f - wx1;
    const float wy1 = iy - y0f;
    const float wy0 = 1.0f - wy1;

    const bool vx0 = (x0 >= 0) & (x0 < GS_W);
    const bool vx1 = (x1 >= 0) & (x1 < GS_W);
    const bool vy0 = (y0 >= 0) & (y0 < GS_H);
    const bool vy1 = (y1 >= 0) & (y1 < GS_H);

    const float w00 = (vx0 & vy0) ? (wy0 * wx0) : 0.0f;
    const float w01 = (vx1 & vy0) ? (wy0 * wx1) : 0.0f;
    const float w10 = (vx0 & vy1) ? (wy1 * wx0) : 0.0f;
    const float w11 = (vx1 & vy1) ? (wy1 * wx1) : 0.0f;

    // Window indices; weight-0 corners clamp into the staged region (rows < h).
    const int i0 = min(max(x0 - cbx, 0), BOXW - 1);
    const int i1 = min(max(x1 - cbx, 0), BOXW - 1);
    const int j0 = min(max(y0 - cby, 0), h - 1);
    const int j1 = min(max(y1 - cby, 0), h - 1);

    const int o00 = j0 * BOXW + i0;
    const int o01 = j0 * BOXW + i1;
    const int o10 = j1 * BOXW + i0;
    const int o11 = j1 * BOXW + i1;

    const int oidx = base + y * GS_W + x;

    // ---- pipelined consume: wait one group, sample its 2 channels ----
    #define SAMPLE_CH(CH)                                                     \
    {                                                                         \
        const float* __restrict__ t = tile + (CH) * CPLANE;                   \
        const float v = w00 * t[o00] + w01 * t[o01]                           \
                      + w10 * t[o10] + w11 * t[o11];                          \
        out[oidx + (CH) * plane] = v;                                         \
    }

    asm volatile("cp.async.wait_group 3;" ::: "memory");
    __syncthreads();
    SAMPLE_CH(0) SAMPLE_CH(1)

    asm volatile("cp.async.wait_group 2;" ::: "memory");
    __syncthreads();
    SAMPLE_CH(2) SAMPLE_CH(3)

    asm volatile("cp.async.wait_group 1;" ::: "memory");
    __syncthreads();
    SAMPLE_CH(4) SAMPLE_CH(5)

    asm volatile("cp.async.wait_group 0;" ::: "memory");
    __syncthreads();
    SAMPLE_CH(6) SAMPLE_CH(7)

    #undef SAMPLE_CH
}

extern "C" void kernel_launch(void* const* d_in, const int* in_sizes, int n_in,
                              void* d_out, int out_size) {
    const float* img    = (const float*)d_in[0];
    const float* params = (const float*)d_in[1];
    float* out = (float*)d_out;

    cudaFuncSetAttribute(GridSampler_kernel,
                         cudaFuncAttributeMaxDynamicSharedMemorySize, SMEM_BYTES);

    dim3 block(1024);
    dim3 grid(GS_W / TILE, GS_H / TILE, GS_B);  // 16 x 16 x 16 = 4096 blocks
    GridSampler_kernel<<<grid, block, SMEM_BYTES>>>(img, params, out);
}

// round 17
// speedup vs baseline: 2.6280x; 1.0354x over previous
#include <cuda_runtime.h>
#include <cuda_bf16.h>
#include <cstdint>

// GridSampler: out[b,c,y,x] = bilinear(img[b,c], affine_grid(params[b])(y,x))
// img: (16, 8, 512, 512) fp32; params: (16, 3) fp32; out: (16, 8, 512, 512) fp32.
//
// R16: (a) 16x2 lane patch -> warp STG = 2 aligned 64B segments (2 L1
// wavefronts vs 4 with the 8x4 patch); (b) 8 cp.async groups of 1 channel,
// consumed wait_group 7..0 with one channel sampled per stage (finer
// stage/sample overlap, exposed latency ~ first 10KB only).

#define GS_B 16
#define GS_C 8
#define GS_H 512
#define GS_W 512

#define TILE 32                      // 32x32 output tile
#define BOXW 52                      // 13 x 16B chunks; covers col span<=48 (+<=3 align)
#define BOXH 48                      // covers row span<=48
#define CHUNKW 13
#define CPLANE (BOXW * BOXH)         // 2496 floats per channel
#define SMEM_BYTES (GS_C * CPLANE * 4)   // 79872 B
#define ROW_THREADS (CHUNKW * BOXH)  // 624 staging threads

__device__ __forceinline__ uint32_t smem_u32(const void* p) {
    uint32_t a;
    asm("{ .reg .u64 t; cvta.to.shared.u64 t, %1; cvt.u32.u64 %0, t; }"
        : "=r"(a) : "l"(p));
    return a;
}

__global__ __launch_bounds__(1024, 2) void GridSampler_kernel(
    const float* __restrict__ img,
    const float* __restrict__ params,
    float* __restrict__ out)
{
    extern __shared__ float tile[];          // [8][48][52] floats

    const int tid  = threadIdx.x;
    const int lane = tid & 31;
    const int warp = tid >> 5;               // 0..31
    // 16x2 lane patch; warps arranged 2x16 over the 32x32 tile.
    // Warp STG: 2 rows x 16 consecutive floats (64B, 64B-aligned) = 2 wavefronts.
    const int lx = lane & 15;
    const int ly = lane >> 4;                // 0..1
    const int wx = (warp & 1) << 4;          // 0,16
    const int wy = (warp >> 1) << 1;         // 0,2,...,30

    const int X0 = blockIdx.x * TILE;
    const int Y0 = blockIdx.y * TILE;
    const int b  = blockIdx.z;
    const int x  = X0 + wx + lx;
    const int y  = Y0 + wy + ly;

    // Per-batch affine params
    const float tx = __ldg(&params[b * 3 + 0]) * (1.0f / (float)GS_W);
    const float ty = __ldg(&params[b * 3 + 1]) * (1.0f / (float)GS_H);
    const float th = __ldg(&params[b * 3 + 2]);
    float s, c;
    sincosf(th, &s, &c);

    auto sample_coord = [&](int px, int py, float& oix, float& oiy) {
        const float xs = (2.0f * (float)px + 1.0f) * (1.0f / (float)GS_W) - 1.0f;
        const float ys = (2.0f * (float)py + 1.0f) * (1.0f / (float)GS_H) - 1.0f;
        const float gx = c * xs - s * ys + tx;
        const float gy = s * xs + c * ys + ty;
        oix = ((gx + 1.0f) * (float)GS_W - 1.0f) * 0.5f;
        oiy = ((gy + 1.0f) * (float)GS_H - 1.0f) * 0.5f;
    };

    // Analytic footprint bbox via affine Jacobian; margins -1/+2 absorb fp delta.
    float ix00, iy00;
    sample_coord(X0, Y0, ix00, iy00);
    const float ec = 31.0f * c;
    const float es = 31.0f * s;
    const float ixmin = ix00 + fminf(ec, 0.0f) + fminf(-es, 0.0f);
    const float iymin = iy00 + fminf(es, 0.0f) + fminf(ec, 0.0f);
    const float iymax = iy00 + fmaxf(es, 0.0f) + fmaxf(ec, 0.0f);

    const int bx0 = (int)floorf(ixmin) - 1;
    const int by0 = (int)floorf(iymin) - 1;
    const int by1 = (int)floorf(iymax) + 2;
    const int h   = min(by1 - by0 + 1, BOXH);        // <= 48 by construction

    const int cbx = min(max(bx0 & ~3, 0), GS_W - BOXW);
    const int cby = min(max(by0, 0), GS_H - h);

    const int plane = GS_H * GS_W;
    const int base  = b * GS_C * plane;

    // ---- Stage: 8 cp.async groups of 1 channel each ----
    const bool do_stage0 = (tid < ROW_THREADS);
    int r = 0, cc = 0;
    if (do_stage0) { r = tid / CHUNKW; cc = tid - r * CHUNKW; }
    const bool do_stage = do_stage0 && (r < h);
    const float* g0 = img + base + (cby + r) * GS_W + cbx + (cc << 2);
    uint32_t sa0 = smem_u32(tile) + (uint32_t)(r * BOXW + (cc << 2)) * 4u;

    #pragma unroll
    for (int grp = 0; grp < 8; grp++) {
        if (do_stage) {
            asm volatile("cp.async.cg.shared.global [%0], [%1], 16;"
                         :: "r"(sa0 + (uint32_t)grp * (CPLANE * 4u)),
                            "l"(g0 + grp * plane) : "memory");
        }
        asm volatile("cp.async.commit_group;" ::: "memory");  // uniform across block
    }

    // ---- per-pixel weights/indices while group 0 is in flight ----
    float ix, iy;
    sample_coord(x, y, ix, iy);

    const float x0f = floorf(ix);
    const float y0f = floorf(iy);
    const int x0 = (int)x0f;
    const int y0 = (int)y0f;
    const int x1 = x0 + 1;
    const int y1 = y0 + 1;

    const float wx1 = ix - x0f;
    const float wx0 = 1.0f - wx1;
    const float wy1 = iy - y0f;
    const float wy0 = 1.0f - wy1;

    const bool vx0 = (x0 >= 0) & (x0 < GS_W);
    const bool vx1 = (x1 >= 0) & (x1 < GS_W);
    const bool vy0 = (y0 >= 0) & (y0 < GS_H);
    const bool vy1 = (y1 >= 0) & (y1 < GS_H);

    const float w00 = (vx0 & vy0) ? (wy0 * wx0) : 0.0f;
    const float w01 = (vx1 & vy0) ? (wy0 * wx1) : 0.0f;
    const float w10 = (vx0 & vy1) ? (wy1 * wx0) : 0.0f;
    const float w11 = (vx1 & vy1) ? (wy1 * wx1) : 0.0f;

    // Window indices; weight-0 corners clamp into the staged region (rows < h).
    const int i0 = min(max(x0 - cbx, 0), BOXW - 1);
    const int i1 = min(max(x1 - cbx, 0), BOXW - 1);
    const int j0 = min(max(y0 - cby, 0), h - 1);
    const int j1 = min(max(y1 - cby, 0), h - 1);

    const int o00 = j0 * BOXW + i0;
    const int o01 = j0 * BOXW + i1;
    const int o10 = j1 * BOXW + i0;
    const int o11 = j1 * BOXW + i1;

    const int oidx = base + y * GS_W + x;

    // ---- pipelined consume: wait one group, sample its channel ----
    #define SAMPLE_STAGE(CH, N)                                               \
    {                                                                         \
        asm volatile("cp.async.wait_group " #N ";" ::: "memory");             \
        __syncthreads();                                                      \
        const float* __restrict__ t = tile + (CH) * CPLANE;                   \
        const float v = w00 * t[o00] + w01 * t[o01]                           \
                      + w10 * t[o10] + w11 * t[o11];                          \
        out[oidx + (CH) * plane] = v;                                         \
    }

    SAMPLE_STAGE(0, 7)
    SAMPLE_STAGE(1, 6)
    SAMPLE_STAGE(2, 5)
    SAMPLE_STAGE(3, 4)
    SAMPLE_STAGE(4, 3)
    SAMPLE_STAGE(5, 2)
    SAMPLE_STAGE(6, 1)
    SAMPLE_STAGE(7, 0)

    #undef SAMPLE_STAGE
}

extern "C" void kernel_launch(void* const* d_in, const int* in_sizes, int n_in,
                              void* d_out, int out_size) {
    const float* img    = (const float*)d_in[0];
    const float* params = (const float*)d_in[1];
    float* out = (float*)d_out;

    cudaFuncSetAttribute(GridSampler_kernel,
                         cudaFuncAttributeMaxDynamicSharedMemorySize, SMEM_BYTES);

    dim3 block(1024);
    dim3 grid(GS_W / TILE, GS_H / TILE, GS_B);  // 16 x 16 x 16 = 4096 blocks
    GridSampler_kernel<<<grid, block, SMEM_BYTES>>>(img, params, out);
}